// round 1
// baseline (speedup 1.0000x reference)
#include <cuda_runtime.h>

#define SEQ   4096
#define BATCH 2
#define HEADS 4
#define DEP   32
#define DM    128
#define NROWS (BATCH*SEQ)

// Scratch (head-split layout [B*H][S][DEP] for Q/K/V; [B*S][DM] for attn out)
__device__ float g_Q[BATCH*HEADS*SEQ*DEP];
__device__ float g_K[BATCH*HEADS*SEQ*DEP];
__device__ float g_V[BATCH*HEADS*SEQ*DEP];
__device__ float g_A[BATCH*SEQ*DM];

// out[row][j] = sum_k X[row][k] * W[k][j] + bias[j]
// headsplit: write to [(b*H+h)*S + s][d] layout (h=j/32, d=j%32)
__global__ __launch_bounds__(128) void proj_kernel(
    const float* __restrict__ X, const float* __restrict__ W,
    const float* __restrict__ bias, float* __restrict__ out, int headsplit)
{
    __shared__ float xs[16][DM];
    const int tid  = threadIdx.x;
    const int row0 = blockIdx.x * 16;

    // load 16 rows of X (2048 floats = 512 float4)
    const float4* Xg  = (const float4*)(X + (size_t)row0 * DM);
    float4*       xs4 = (float4*)xs;
#pragma unroll
    for (int i = 0; i < 4; i++) xs4[tid + 128 * i] = Xg[tid + 128 * i];
    __syncthreads();

    const int j = tid;
    float acc[16];
#pragma unroll
    for (int r = 0; r < 16; r++) acc[r] = 0.f;

#pragma unroll 4
    for (int k4 = 0; k4 < DM / 4; k4++) {
        const float w0 = W[(k4 * 4 + 0) * DM + j];
        const float w1 = W[(k4 * 4 + 1) * DM + j];
        const float w2 = W[(k4 * 4 + 2) * DM + j];
        const float w3 = W[(k4 * 4 + 3) * DM + j];
#pragma unroll
        for (int r = 0; r < 16; r++) {
            const float4 x4 = *(const float4*)&xs[r][k4 * 4];
            acc[r] += x4.x * w0 + x4.y * w1 + x4.z * w2 + x4.w * w3;
        }
    }

    const float bj = bias[j];
    if (headsplit) {
        const int h = j >> 5, d = j & 31;
#pragma unroll
        for (int r = 0; r < 16; r++) {
            const int row = row0 + r;
            const int b = row >> 12, s = row & (SEQ - 1);
            g_QKV_dummy: ;
            out[((((b * HEADS + h) * SEQ) + s) << 5) + d] = acc[r] + bj;
        }
    } else {
#pragma unroll
        for (int r = 0; r < 16; r++)
            out[(size_t)(row0 + r) * DM + j] = acc[r] + bj;
    }
}

// Flash attention, fp32. 1 thread = 1 query row, BM=128 rows/block, BN=32 KV tile.
__global__ __launch_bounds__(128) void attn_kernel(
    const float* __restrict__ gQ, const float* __restrict__ gK,
    const float* __restrict__ gV, float* __restrict__ gO)
{
    __shared__ float Ks[32 * DEP];
    __shared__ float Vs[32 * DEP];

    const int tid  = threadIdx.x;
    const int bh   = blockIdx.y;                 // b*HEADS + h
    const int qrow = blockIdx.x * 128 + tid;
    const float scale = 0.17677669529663687f;    // 1/sqrt(32)

    // load Q row into registers, pre-scaled
    const float4* qptr = (const float4*)(gQ + ((size_t)bh * SEQ + qrow) * DEP);
    float4 q4[8];
#pragma unroll
    for (int i = 0; i < 8; i++) {
        q4[i] = qptr[i];
        q4[i].x *= scale; q4[i].y *= scale; q4[i].z *= scale; q4[i].w *= scale;
    }

    float4 o4[8];
#pragma unroll
    for (int i = 0; i < 8; i++) o4[i] = make_float4(0.f, 0.f, 0.f, 0.f);
    float m = -1e30f, l = 0.f;

    const float4* Kb  = (const float4*)(gK + (size_t)bh * SEQ * DEP);
    const float4* Vb  = (const float4*)(gV + (size_t)bh * SEQ * DEP);
    float4* Ks4 = (float4*)Ks;
    float4* Vs4 = (float4*)Vs;

    for (int t = 0; t < SEQ / 32; t++) {
        const int base = t * 256;              // 32 rows * 8 float4
        Ks4[tid]       = Kb[base + tid];
        Ks4[tid + 128] = Kb[base + tid + 128];
        Vs4[tid]       = Vb[base + tid];
        Vs4[tid + 128] = Vb[base + tid + 128];
        __syncthreads();

        // logits for 32 KV columns
        float sreg[32];
#pragma unroll
        for (int c = 0; c < 32; c++) {
            float acc = 0.f;
#pragma unroll
            for (int d = 0; d < 8; d++) {
                const float4 k4 = Ks4[c * 8 + d];     // warp-broadcast
                acc += q4[d].x * k4.x + q4[d].y * k4.y
                     + q4[d].z * k4.z + q4[d].w * k4.w;
            }
            sreg[c] = acc;
        }

        // online softmax update
        float mt = m;
#pragma unroll
        for (int c = 0; c < 32; c++) mt = fmaxf(mt, sreg[c]);
        const float alpha = __expf(m - mt);
        m = mt;
        l *= alpha;
#pragma unroll
        for (int i = 0; i < 8; i++) {
            o4[i].x *= alpha; o4[i].y *= alpha;
            o4[i].z *= alpha; o4[i].w *= alpha;
        }

#pragma unroll
        for (int c = 0; c < 32; c++) {
            const float p = __expf(sreg[c] - m);
            l += p;
#pragma unroll
            for (int d = 0; d < 8; d++) {
                const float4 v4 = Vs4[c * 8 + d];     // warp-broadcast
                o4[d].x += p * v4.x; o4[d].y += p * v4.y;
                o4[d].z += p * v4.z; o4[d].w += p * v4.w;
            }
        }
        __syncthreads();
    }

    const float inv = 1.f / l;
    const int b = bh >> 2, h = bh & 3;
    float4* optr = (float4*)(gO + ((size_t)(b * SEQ + qrow) * DM) + h * DEP);
#pragma unroll
    for (int i = 0; i < 8; i++) {
        float4 r = o4[i];
        r.x *= inv; r.y *= inv; r.z *= inv; r.w *= inv;
        optr[i] = r;
    }
}

extern "C" void kernel_launch(void* const* d_in, const int* in_sizes, int n_in,
                              void* d_out, int out_size)
{
    const float* q  = (const float*)d_in[0];
    const float* k  = (const float*)d_in[1];
    const float* v  = (const float*)d_in[2];
    const float* Wq = (const float*)d_in[3];
    const float* bq = (const float*)d_in[4];
    const float* Wk = (const float*)d_in[5];
    const float* bk = (const float*)d_in[6];
    const float* Wv = (const float*)d_in[7];
    const float* bv = (const float*)d_in[8];
    const float* Wo = (const float*)d_in[9];
    const float* bo = (const float*)d_in[10];
    float* out = (float*)d_out;

    float *gq, *gk, *gv, *ga;
    cudaGetSymbolAddress((void**)&gq, g_Q);
    cudaGetSymbolAddress((void**)&gk, g_K);
    cudaGetSymbolAddress((void**)&gv, g_V);
    cudaGetSymbolAddress((void**)&ga, g_A);

    const int pblocks = NROWS / 16;   // 512
    proj_kernel<<<pblocks, 128>>>(q, Wq, bq, gq, 1);
    proj_kernel<<<pblocks, 128>>>(k, Wk, bk, gk, 1);
    proj_kernel<<<pblocks, 128>>>(v, Wv, bv, gv, 1);

    dim3 agrid(SEQ / 128, BATCH * HEADS);     // (32, 8)
    attn_kernel<<<agrid, 128>>>(gq, gk, gv, ga);

    proj_kernel<<<pblocks, 128>>>(ga, Wo, bo, out, 0);
}

// round 3
// speedup vs baseline: 1.2723x; 1.2723x over previous
#include <cuda_runtime.h>

#define SEQ   4096
#define BATCH 2
#define HEADS 4
#define BH    (BATCH*HEADS)
#define DEP   32
#define DM    128
#define NROWS (BATCH*SEQ)
#define NS    4
#define CHUNK (SEQ/NS)
#define BM    128
#define BN    32

// Scratch
__device__ float g_Q[BH*SEQ*DEP];
__device__ float g_K[BH*SEQ*DEP];
__device__ float g_V[BH*SEQ*DEP];
__device__ float g_A[NROWS*DM];
__device__ float g_Po[NS*BH*SEQ*DEP];
__device__ float g_Pm[NS*BH*SEQ];
__device__ float g_Pl[NS*BH*SEQ];

typedef unsigned long long u64;

__device__ __forceinline__ void ffma2(u64& d, u64 a, u64 b) {
    asm("fma.rn.f32x2 %0, %1, %2, %0;" : "+l"(d) : "l"(a), "l"(b));
}
__device__ __forceinline__ void fmul2(u64& d, u64 a, u64 b) {
    asm("mul.rn.f32x2 %0, %1, %2;" : "=l"(d) : "l"(a), "l"(b));
}
__device__ __forceinline__ u64 pack2(float lo, float hi) {
    u64 r; asm("mov.b64 %0, {%1, %2};" : "=l"(r) : "f"(lo), "f"(hi)); return r;
}
__device__ __forceinline__ void unpack2(u64 v, float& lo, float& hi) {
    asm("mov.b64 {%0, %1}, %2;" : "=f"(lo), "=f"(hi) : "l"(v));
}

// out[row][j] = sum_k X[row][k]*W[k][j] + bias[j]
__global__ __launch_bounds__(128) void proj_kernel(
    const float* __restrict__ X, const float* __restrict__ W,
    const float* __restrict__ bias, float* __restrict__ out, int headsplit)
{
    __shared__ __align__(16) float xs[16][DM];
    const int tid  = threadIdx.x;
    const int row0 = blockIdx.x * 16;

    const float4* Xg  = (const float4*)(X + (size_t)row0 * DM);
    float4*       xs4 = (float4*)xs;
#pragma unroll
    for (int i = 0; i < 4; i++) xs4[tid + 128 * i] = Xg[tid + 128 * i];
    __syncthreads();

    const int j = tid;
    float acc[16];
#pragma unroll
    for (int r = 0; r < 16; r++) acc[r] = 0.f;

#pragma unroll 4
    for (int k4 = 0; k4 < DM / 4; k4++) {
        const float w0 = W[(k4 * 4 + 0) * DM + j];
        const float w1 = W[(k4 * 4 + 1) * DM + j];
        const float w2 = W[(k4 * 4 + 2) * DM + j];
        const float w3 = W[(k4 * 4 + 3) * DM + j];
#pragma unroll
        for (int r = 0; r < 16; r++) {
            const float4 x4 = *(const float4*)&xs[r][k4 * 4];
            acc[r] += x4.x * w0 + x4.y * w1 + x4.z * w2 + x4.w * w3;
        }
    }

    const float bj = bias[j];
    if (headsplit) {
        const int h = j >> 5, d = j & 31;
#pragma unroll
        for (int r = 0; r < 16; r++) {
            const int row = row0 + r;
            const int b = row >> 12, s = row & (SEQ - 1);
            out[((((b * HEADS + h) * SEQ) + s) << 5) + d] = acc[r] + bj;
        }
    } else {
#pragma unroll
        for (int r = 0; r < 16; r++)
            out[(size_t)(row0 + r) * DM + j] = acc[r] + bj;
    }
}

// Flash attention partial over one KV chunk. 1 thread = 1 query row.
// Packed f32x2 math throughout. Writes unnormalized (o, m, l).
__global__ __launch_bounds__(128, 3) void attn_kernel(
    const float* __restrict__ gQ, const float* __restrict__ gK,
    const float* __restrict__ gV, float* __restrict__ Po,
    float* __restrict__ Pm, float* __restrict__ Pl)
{
    __shared__ __align__(16) float Ks[BN * DEP];
    __shared__ __align__(16) float Vs[BN * DEP];

    const int tid   = threadIdx.x;
    const int bh    = blockIdx.y;
    const int chunk = blockIdx.z;
    const int qrow  = blockIdx.x * BM + tid;
    const float scale = 0.17677669529663687f;   // 1/sqrt(32)

    const float4* qptr = (const float4*)(gQ + ((size_t)bh * SEQ + qrow) * DEP);
    u64 q2[16];
#pragma unroll
    for (int i = 0; i < 8; i++) {
        float4 qa = qptr[i];
        q2[2*i]   = pack2(qa.x * scale, qa.y * scale);
        q2[2*i+1] = pack2(qa.z * scale, qa.w * scale);
    }

    u64 o2[16];
    const u64 zero2 = pack2(0.f, 0.f);
#pragma unroll
    for (int i = 0; i < 16; i++) o2[i] = zero2;
    float m = -1e30f, l = 0.f;

    const float4* Kb = (const float4*)(gK + ((size_t)bh * SEQ + (size_t)chunk * CHUNK) * DEP);
    const float4* Vb = (const float4*)(gV + ((size_t)bh * SEQ + (size_t)chunk * CHUNK) * DEP);
    float4* Ks4 = (float4*)Ks;
    float4* Vs4 = (float4*)Vs;

#pragma unroll 1
    for (int t = 0; t < CHUNK / BN; t++) {
        const int base = t * 256;                 // 32 rows * 8 float4
        Ks4[tid]       = Kb[base + tid];
        Ks4[tid + 128] = Kb[base + tid + 128];
        Vs4[tid]       = Vb[base + tid];
        Vs4[tid + 128] = Vb[base + tid + 128];
        __syncthreads();

        float sreg[BN];
#pragma unroll
        for (int c = 0; c < BN; c++) {
            const ulonglong2* kc = (const ulonglong2*)(Ks + c * DEP);
            u64 a0 = zero2, a1 = zero2;
#pragma unroll
            for (int d = 0; d < 8; d++) {
                ulonglong2 kk = kc[d];            // LDS.128 broadcast
                ffma2(a0, q2[2*d],   kk.x);
                ffma2(a1, q2[2*d+1], kk.y);
            }
            float l0, h0, l1, h1;
            unpack2(a0, l0, h0);
            unpack2(a1, l1, h1);
            sreg[c] = (l0 + h0) + (l1 + h1);
        }

        float mt = m;
#pragma unroll
        for (int c = 0; c < BN; c++) mt = fmaxf(mt, sreg[c]);
        const float alpha = __expf(m - mt);
        m = mt;
        l *= alpha;
        const u64 al2 = pack2(alpha, alpha);
#pragma unroll
        for (int i = 0; i < 16; i++) fmul2(o2[i], o2[i], al2);

#pragma unroll
        for (int c = 0; c < BN; c++) {
            const float p = __expf(sreg[c] - m);
            l += p;
            const u64 p2 = pack2(p, p);
            const ulonglong2* vc = (const ulonglong2*)(Vs + c * DEP);
#pragma unroll
            for (int d = 0; d < 8; d++) {
                ulonglong2 vv = vc[d];            // LDS.128 broadcast
                ffma2(o2[2*d],   p2, vv.x);
                ffma2(o2[2*d+1], p2, vv.y);
            }
        }
        __syncthreads();
    }

    const size_t pidx = (size_t)(chunk * BH + bh) * SEQ + qrow;
    float4* po4 = (float4*)(Po + pidx * DEP);
#pragma unroll
    for (int i = 0; i < 8; i++) {
        float x, y, z, w;
        unpack2(o2[2*i],   x, y);
        unpack2(o2[2*i+1], z, w);
        po4[i] = make_float4(x, y, z, w);
    }
    Pm[pidx] = m;
    Pl[pidx] = l;
}

// Merge NS partials per query row, write normalized attn output (interleaved heads).
__global__ __launch_bounds__(256) void combine_kernel(
    const float* __restrict__ Po, const float* __restrict__ Pm,
    const float* __restrict__ Pl, float* __restrict__ gA)
{
    const int idx = blockIdx.x * 256 + threadIdx.x;   // bh*SEQ + row
    const int bh  = idx >> 12;
    const int row = idx & (SEQ - 1);

    float mv[NS];
    float mstar = -1e30f;
#pragma unroll
    for (int ns = 0; ns < NS; ns++) {
        mv[ns] = Pm[(size_t)ns * BH * SEQ + idx];
        mstar = fmaxf(mstar, mv[ns]);
    }
    float w[NS];
    float L = 0.f;
#pragma unroll
    for (int ns = 0; ns < NS; ns++) {
        w[ns] = __expf(mv[ns] - mstar);
        L += Pl[(size_t)ns * BH * SEQ + idx] * w[ns];
    }
    const float inv = 1.f / L;

    float4 acc[8];
#pragma unroll
    for (int i = 0; i < 8; i++) acc[i] = make_float4(0.f, 0.f, 0.f, 0.f);
#pragma unroll
    for (int ns = 0; ns < NS; ns++) {
        const float4* p = (const float4*)(Po + ((size_t)ns * BH * SEQ + idx) * DEP);
        const float ww = w[ns];
#pragma unroll
        for (int i = 0; i < 8; i++) {
            float4 v = p[i];
            acc[i].x += v.x * ww; acc[i].y += v.y * ww;
            acc[i].z += v.z * ww; acc[i].w += v.w * ww;
        }
    }

    const int b = bh >> 2, h = bh & 3;
    float4* outp = (float4*)(gA + ((size_t)(b * SEQ + row)) * DM + h * DEP);
#pragma unroll
    for (int i = 0; i < 8; i++) {
        float4 r = acc[i];
        r.x *= inv; r.y *= inv; r.z *= inv; r.w *= inv;
        outp[i] = r;
    }
}

extern "C" void kernel_launch(void* const* d_in, const int* in_sizes, int n_in,
                              void* d_out, int out_size)
{
    const float* q  = (const float*)d_in[0];
    const float* k  = (const float*)d_in[1];
    const float* v  = (const float*)d_in[2];
    const float* Wq = (const float*)d_in[3];
    const float* bq = (const float*)d_in[4];
    const float* Wk = (const float*)d_in[5];
    const float* bk = (const float*)d_in[6];
    const float* Wv = (const float*)d_in[7];
    const float* bv = (const float*)d_in[8];
    const float* Wo = (const float*)d_in[9];
    const float* bo = (const float*)d_in[10];
    float* out = (float*)d_out;

    float *gq, *gk, *gv, *ga, *gpo, *gpm, *gpl;
    cudaGetSymbolAddress((void**)&gq,  g_Q);
    cudaGetSymbolAddress((void**)&gk,  g_K);
    cudaGetSymbolAddress((void**)&gv,  g_V);
    cudaGetSymbolAddress((void**)&ga,  g_A);
    cudaGetSymbolAddress((void**)&gpo, g_Po);
    cudaGetSymbolAddress((void**)&gpm, g_Pm);
    cudaGetSymbolAddress((void**)&gpl, g_Pl);

    const int pblocks = NROWS / 16;   // 512
    proj_kernel<<<pblocks, 128>>>(q, Wq, bq, gq, 1);
    proj_kernel<<<pblocks, 128>>>(k, Wk, bk, gk, 1);
    proj_kernel<<<pblocks, 128>>>(v, Wv, bv, gv, 1);

    dim3 agrid(SEQ / BM, BH, NS);     // (32, 8, 4) = 1024 blocks
    attn_kernel<<<agrid, 128>>>(gq, gk, gv, gpo, gpm, gpl);

    combine_kernel<<<BH * SEQ / 256, 256>>>(gpo, gpm, gpl, ga);

    proj_kernel<<<pblocks, 128>>>(ga, Wo, bo, out, 0);
}

// round 4
// speedup vs baseline: 2.1640x; 1.7009x over previous
#include <cuda_runtime.h>

#define SEQ   4096
#define BATCH 2
#define HEADS 4
#define BH    (BATCH*HEADS)
#define DEP   32
#define DM    128
#define NROWS (BATCH*SEQ)
#define BN    64            // kv tile
#define WM    16            // q rows per warp
#define NWARP 4
#define BM    (WM*NWARP)    // 64 q rows per block
#define KPAD  36            // smem row stride (floats): bank = (4*gid+tig)%32 distinct

// Scratch
__device__ float g_Q[BH*SEQ*DEP];
__device__ float g_K[BH*SEQ*DEP];
__device__ float g_V[BH*SEQ*DEP];
__device__ float g_A[NROWS*DM];

__device__ __forceinline__ unsigned f2tf(float x) {
    unsigned r; asm("cvt.rna.tf32.f32 %0, %1;" : "=r"(r) : "f"(x)); return r;
}
__device__ __forceinline__ void mma_tf32(float* d, const unsigned* a, const unsigned* b) {
    asm volatile("mma.sync.aligned.m16n8k8.row.col.f32.tf32.tf32.f32 "
        "{%0,%1,%2,%3}, {%4,%5,%6,%7}, {%8,%9}, {%0,%1,%2,%3};"
        : "+f"(d[0]), "+f"(d[1]), "+f"(d[2]), "+f"(d[3])
        : "r"(a[0]), "r"(a[1]), "r"(a[2]), "r"(a[3]), "r"(b[0]), "r"(b[1]));
}

// out[row][j] = sum_k X[row][k]*W[k][j] + bias[j]
__global__ __launch_bounds__(128) void proj_kernel(
    const float* __restrict__ X, const float* __restrict__ W,
    const float* __restrict__ bias, float* __restrict__ out, int headsplit)
{
    __shared__ __align__(16) float xs[16][DM];
    const int tid  = threadIdx.x;
    const int row0 = blockIdx.x * 16;

    const float4* Xg  = (const float4*)(X + (size_t)row0 * DM);
    float4*       xs4 = (float4*)xs;
#pragma unroll
    for (int i = 0; i < 4; i++) xs4[tid + 128 * i] = Xg[tid + 128 * i];
    __syncthreads();

    const int j = tid;
    float acc[16];
#pragma unroll
    for (int r = 0; r < 16; r++) acc[r] = 0.f;

#pragma unroll 4
    for (int k4 = 0; k4 < DM / 4; k4++) {
        const float w0 = W[(k4 * 4 + 0) * DM + j];
        const float w1 = W[(k4 * 4 + 1) * DM + j];
        const float w2 = W[(k4 * 4 + 2) * DM + j];
        const float w3 = W[(k4 * 4 + 3) * DM + j];
#pragma unroll
        for (int r = 0; r < 16; r++) {
            const float4 x4 = *(const float4*)&xs[r][k4 * 4];
            acc[r] += x4.x * w0 + x4.y * w1 + x4.z * w2 + x4.w * w3;
        }
    }

    const float bj = bias[j];
    if (headsplit) {
        const int h = j >> 5, d = j & 31;
#pragma unroll
        for (int r = 0; r < 16; r++) {
            const int row = row0 + r;
            const int b = row >> 12, s = row & (SEQ - 1);
            out[((((b * HEADS + h) * SEQ) + s) << 5) + d] = acc[r] + bj;
        }
    } else {
#pragma unroll
        for (int r = 0; r < 16; r++)
            out[(size_t)(row0 + r) * DM + j] = acc[r] + bj;
    }
}

// Flash attention with tf32 mma.sync. Block = 64 q rows (4 warps x m16), KV tile 64.
// QK^T uses 2-term tf32 split (error ~2^-22); PV single tf32.
__global__ __launch_bounds__(128, 2) void attn_kernel(
    const float* __restrict__ gQ, const float* __restrict__ gK,
    const float* __restrict__ gV, float* __restrict__ gA)
{
    __shared__ __align__(16) float Ks[BN * KPAD];
    __shared__ __align__(16) float Vs[BN * KPAD];

    const int tid  = threadIdx.x;
    const int wid  = tid >> 5;
    const int lane = tid & 31;
    const int gid  = lane >> 2;   // 0..7
    const int tig  = lane & 3;    // 0..3
    const int bh   = blockIdx.y;
    const int q0   = blockIdx.x * BM + wid * WM;
    const float scale = 0.17677669529663687f;   // 1/sqrt(32)

    // ---- Q fragments (A-layout, per k-chunk of 8), 2-term split, pre-scaled ----
    unsigned qh[4][4], ql[4][4];
    {
        const float* Qb = gQ + ((size_t)bh * SEQ + q0) * DEP;
#pragma unroll
        for (int kc = 0; kc < 4; kc++) {
            const int d0 = kc * 8;
            float v[4];
            v[0] = Qb[(size_t)gid       * DEP + d0 + tig    ] * scale;
            v[1] = Qb[(size_t)(gid + 8) * DEP + d0 + tig    ] * scale;
            v[2] = Qb[(size_t)gid       * DEP + d0 + tig + 4] * scale;
            v[3] = Qb[(size_t)(gid + 8) * DEP + d0 + tig + 4] * scale;
#pragma unroll
            for (int i = 0; i < 4; i++) {
                qh[kc][i] = f2tf(v[i]);
                ql[kc][i] = __float_as_uint(v[i] - __uint_as_float(qh[kc][i]));
            }
        }
    }

    float o[4][4];
#pragma unroll
    for (int i = 0; i < 4; i++)
#pragma unroll
        for (int j = 0; j < 4; j++) o[i][j] = 0.f;
    float m0 = -1e30f, m1 = -1e30f, l0 = 0.f, l1 = 0.f;

    const float* Kb = gK + (size_t)bh * SEQ * DEP;
    const float* Vb = gV + (size_t)bh * SEQ * DEP;

    const int src0 = (lane & ~3) | (tig >> 1);
    const int src1 = src0 + 2;
    const int esel = tig & 1;

#pragma unroll 1
    for (int t = 0; t < SEQ / BN; t++) {
        // ---- cooperative load K,V tile [64 x 32] into padded smem ----
        {
            const float4* Ksrc = (const float4*)(Kb + (size_t)t * BN * DEP);
            const float4* Vsrc = (const float4*)(Vb + (size_t)t * BN * DEP);
#pragma unroll
            for (int i = 0; i < 4; i++) {
                const int idx = tid + i * 128;        // 512 float4 total
                const int r = idx >> 3;
                const int c = (idx & 7) * 4;
                float4 k4 = Ksrc[idx];
                float* dk = Ks + r * KPAD + c;
                dk[0] = k4.x; dk[1] = k4.y; dk[2] = k4.z; dk[3] = k4.w;
                float4 v4 = Vsrc[idx];
                float* dv = Vs + r * KPAD + c;
                dv[0] = v4.x; dv[1] = v4.y; dv[2] = v4.z; dv[3] = v4.w;
            }
        }
        __syncthreads();

        // ---- S = Q K^T  (16 x 64 per warp), split-tf32 ----
        float s[8][4];
#pragma unroll
        for (int nt = 0; nt < 8; nt++) {
            s[nt][0] = s[nt][1] = s[nt][2] = s[nt][3] = 0.f;
#pragma unroll
            for (int kc = 0; kc < 4; kc++) {
                const float k0 = Ks[(nt * 8 + gid) * KPAD + kc * 8 + tig];
                const float k1 = Ks[(nt * 8 + gid) * KPAD + kc * 8 + tig + 4];
                unsigned bhf[2], blf[2];
                bhf[0] = f2tf(k0); blf[0] = __float_as_uint(k0 - __uint_as_float(bhf[0]));
                bhf[1] = f2tf(k1); blf[1] = __float_as_uint(k1 - __uint_as_float(bhf[1]));
                mma_tf32(s[nt], qh[kc], bhf);
                mma_tf32(s[nt], qh[kc], blf);
                mma_tf32(s[nt], ql[kc], bhf);
            }
        }

        // ---- online softmax: row max over 4-lane groups ----
        float mt0 = m0, mt1 = m1;
#pragma unroll
        for (int nt = 0; nt < 8; nt++) {
            mt0 = fmaxf(mt0, fmaxf(s[nt][0], s[nt][1]));
            mt1 = fmaxf(mt1, fmaxf(s[nt][2], s[nt][3]));
        }
        mt0 = fmaxf(mt0, __shfl_xor_sync(0xffffffffu, mt0, 1));
        mt0 = fmaxf(mt0, __shfl_xor_sync(0xffffffffu, mt0, 2));
        mt1 = fmaxf(mt1, __shfl_xor_sync(0xffffffffu, mt1, 1));
        mt1 = fmaxf(mt1, __shfl_xor_sync(0xffffffffu, mt1, 2));
        const float alpha0 = __expf(m0 - mt0);
        const float alpha1 = __expf(m1 - mt1);
        m0 = mt0; m1 = mt1;
        l0 *= alpha0; l1 *= alpha1;
#pragma unroll
        for (int ntd = 0; ntd < 4; ntd++) {
            o[ntd][0] *= alpha0; o[ntd][1] *= alpha0;
            o[ntd][2] *= alpha1; o[ntd][3] *= alpha1;
        }

        // ---- P (A-layout via shfl) + O += P V ----
#pragma unroll
        for (int nt = 0; nt < 8; nt++) {
            // gather S into A-layout for kv chunk nt
            const float x0 = __shfl_sync(0xffffffffu, s[nt][0], src0);
            const float x1 = __shfl_sync(0xffffffffu, s[nt][1], src0);
            const float y0 = __shfl_sync(0xffffffffu, s[nt][2], src0);
            const float y1 = __shfl_sync(0xffffffffu, s[nt][3], src0);
            const float z0 = __shfl_sync(0xffffffffu, s[nt][0], src1);
            const float z1 = __shfl_sync(0xffffffffu, s[nt][1], src1);
            const float w0 = __shfl_sync(0xffffffffu, s[nt][2], src1);
            const float w1 = __shfl_sync(0xffffffffu, s[nt][3], src1);
            const float sa0 = esel ? x1 : x0;   // row gid,   kv col nt*8+tig
            const float sa1 = esel ? y1 : y0;   // row gid+8, kv col nt*8+tig
            const float sa2 = esel ? z1 : z0;   // row gid,   kv col nt*8+tig+4
            const float sa3 = esel ? w1 : w0;   // row gid+8, kv col nt*8+tig+4
            const float p0 = __expf(sa0 - m0);
            const float p1 = __expf(sa1 - m1);
            const float p2 = __expf(sa2 - m0);
            const float p3 = __expf(sa3 - m1);
            l0 += p0 + p2;
            l1 += p1 + p3;
            unsigned pa[4] = { f2tf(p0), f2tf(p1), f2tf(p2), f2tf(p3) };
#pragma unroll
            for (int ntd = 0; ntd < 4; ntd++) {
                unsigned bv[2];
                bv[0] = __float_as_uint(Vs[(nt * 8 + tig)     * KPAD + ntd * 8 + gid]);
                bv[1] = __float_as_uint(Vs[(nt * 8 + tig + 4) * KPAD + ntd * 8 + gid]);
                mma_tf32(o[ntd], pa, bv);
            }
        }
        __syncthreads();
    }

    // ---- finalize: reduce l across the 4-lane group, normalize, store ----
    l0 += __shfl_xor_sync(0xffffffffu, l0, 1);
    l0 += __shfl_xor_sync(0xffffffffu, l0, 2);
    l1 += __shfl_xor_sync(0xffffffffu, l1, 1);
    l1 += __shfl_xor_sync(0xffffffffu, l1, 2);
    const float inv0 = 1.f / l0;
    const float inv1 = 1.f / l1;

    const int b_ = bh >> 2, h_ = bh & 3;
    float* Ob0 = gA + (size_t)(b_ * SEQ + q0 + gid)     * DM + h_ * DEP;
    float* Ob1 = gA + (size_t)(b_ * SEQ + q0 + gid + 8) * DM + h_ * DEP;
#pragma unroll
    for (int ntd = 0; ntd < 4; ntd++) {
        const int d = ntd * 8 + tig * 2;
        *(float2*)(Ob0 + d) = make_float2(o[ntd][0] * inv0, o[ntd][1] * inv0);
        *(float2*)(Ob1 + d) = make_float2(o[ntd][2] * inv1, o[ntd][3] * inv1);
    }
}

extern "C" void kernel_launch(void* const* d_in, const int* in_sizes, int n_in,
                              void* d_out, int out_size)
{
    const float* q  = (const float*)d_in[0];
    const float* k  = (const float*)d_in[1];
    const float* v  = (const float*)d_in[2];
    const float* Wq = (const float*)d_in[3];
    const float* bq = (const float*)d_in[4];
    const float* Wk = (const float*)d_in[5];
    const float* bk = (const float*)d_in[6];
    const float* Wv = (const float*)d_in[7];
    const float* bv = (const float*)d_in[8];
    const float* Wo = (const float*)d_in[9];
    const float* bo = (const float*)d_in[10];
    float* out = (float*)d_out;

    float *gq, *gk, *gv, *ga;
    cudaGetSymbolAddress((void**)&gq, g_Q);
    cudaGetSymbolAddress((void**)&gk, g_K);
    cudaGetSymbolAddress((void**)&gv, g_V);
    cudaGetSymbolAddress((void**)&ga, g_A);

    const int pblocks = NROWS / 16;   // 512
    proj_kernel<<<pblocks, 128>>>(q, Wq, bq, gq, 1);
    proj_kernel<<<pblocks, 128>>>(k, Wk, bk, gk, 1);
    proj_kernel<<<pblocks, 128>>>(v, Wv, bv, gv, 1);

    dim3 agrid(SEQ / BM, BH);   // (64, 8) = 512 blocks
    attn_kernel<<<agrid, 128>>>(gq, gk, gv, ga);

    proj_kernel<<<pblocks, 128>>>(ga, Wo, bo, out, 0);
}